// round 9
// baseline (speedup 1.0000x reference)
#include <cuda_runtime.h>

#define B_DIM 256
#define N_DIM 256
#define EPS_F 1e-7f
#define TAU   0.1f

// Scratch (no allocations allowed anywhere)
__device__ float2       g_tf[B_DIM];
__device__ unsigned int g_ticket;

__device__ __forceinline__ float poly_mlog1m(float x) {
    // Sum_{m=1..4} x^m/m  (approximates -log(1-x))
    return x * fmaf(x, fmaf(x, fmaf(x, 0.25f, 1.0f / 3.0f), 0.5f), 1.0f);
}

// -----------------------------------------------------------------------------
// TWO rows per THREAD (ILP on the latency-bound shfl/LDS chains), 128 blocks
// of 256 threads = single wave. Per row r in {0,1}: warp bitonic sort of
// 64-bit keys, per-run register suffix scan of (e..e^4), suffix-table lookup
// den4, series part2 + exact corrections, warp/block reduce. The two rows'
// chains are independent -> compiler interleaves them, ~2x issue density.
// -----------------------------------------------------------------------------
__global__ void __launch_bounds__(N_DIM) cox_kernel(
    const float* __restrict__ pred,
    const float* __restrict__ target,
    const unsigned int* __restrict__ mask,
    float* __restrict__ out)
{
    const int blk  = blockIdx.x;
    const int i    = threadIdx.x;
    const int lane = i & 31, w8 = i >> 5;

    __shared__ unsigned int skey32[2][N_DIM];
    __shared__ float4       srun[2][8 * 33];
    __shared__ float        s_runmax[2][8];
    __shared__ float2       candTE[2][N_DIM];
    __shared__ int          candI[2][N_DIM];
    __shared__ int          warp_cc[2][8];
    __shared__ int          warp_vc[2][8];
    __shared__ float        sredA[2][8];

    float p[2], tm[2], e[2];
    unsigned int u[2];
    unsigned long long key[2];

    #pragma unroll
    for (int r = 0; r < 2; ++r) {
        const int base = (blk * 2 + r) * N_DIM;
        p[r] = pred[base + i];
        const float t = target[base + i];
        const bool  v = mask[base + i] != 0u;
        tm[r] = v ? t : -1.0f;
        e[r]  = __expf(p[r]);
        const unsigned int bv = __ballot_sync(0xffffffffu, v);
        if (lane == 0) warp_vc[r][w8] = __popc(bv);
        const unsigned int fb = __float_as_uint(tm[r]);
        u[r] = fb ^ ((fb & 0x80000000u) ? 0xFFFFFFFFu : 0x80000000u);
        key[r] = ((unsigned long long)u[r] << 32) | (unsigned int)i;
    }

    // Warp bitonic sorts, both rows interleaved (independent chains)
    #pragma unroll
    for (int k = 2; k <= 32; k <<= 1) {
        #pragma unroll
        for (int j = k >> 1; j > 0; j >>= 1) {
            const bool keepmin = (((lane & j) == 0) == ((lane & k) == 0));
            #pragma unroll
            for (int r = 0; r < 2; ++r) {
                const unsigned long long other = __shfl_xor_sync(0xffffffffu, key[r], j);
                const bool gt = key[r] > other;
                key[r] = (gt == keepmin) ? other : key[r];
            }
        }
    }

    // Payload fetch + per-run suffix scans (both rows interleaved)
    float4 x[2];
    #pragma unroll
    for (int r = 0; r < 2; ++r) {
        const float es = __shfl_sync(0xffffffffu, e[r], (int)key[r] & 31);
        const float e2 = es * es;
        x[r] = make_float4(es, e2, e2 * es, e2 * e2);
    }
    #pragma unroll
    for (int o = 1; o < 32; o <<= 1) {
        #pragma unroll
        for (int r = 0; r < 2; ++r) {
            const float t0 = __shfl_down_sync(0xffffffffu, x[r].x, o);
            const float t1 = __shfl_down_sync(0xffffffffu, x[r].y, o);
            const float t2 = __shfl_down_sync(0xffffffffu, x[r].z, o);
            const float t3 = __shfl_down_sync(0xffffffffu, x[r].w, o);
            if (lane < 32 - o) { x[r].x += t0; x[r].y += t1; x[r].z += t2; x[r].w += t3; }
        }
    }
    #pragma unroll
    for (int r = 0; r < 2; ++r) {
        skey32[r][i] = (unsigned int)(key[r] >> 32);
        srun[r][w8 * 33 + lane] = x[r];
        if (lane == 31) {
            srun[r][w8 * 33 + 32] = make_float4(0.f, 0.f, 0.f, 0.f);
            const unsigned int uu  = (unsigned int)(key[r] >> 32);
            const unsigned int fb2 = (uu & 0x80000000u) ? (uu ^ 0x80000000u) : ~uu;
            s_runmax[r][w8] = __uint_as_float(fb2);
        }
    }
    __syncthreads();                                   // bar1

    // den4 lookups (16 independent searches across both rows)
    float4 den4[2];
    #pragma unroll
    for (int r = 0; r < 2; ++r) den4[r] = make_float4(0.f, 0.f, 0.f, 0.f);
    #pragma unroll
    for (int w = 0; w < 8; ++w) {
        #pragma unroll
        for (int r = 0; r < 2; ++r) {
            const int rb = w * 32;
            int lo = 0;
            #pragma unroll
            for (int s = 16; s; s >>= 1)
                if (skey32[r][rb + lo + s - 1] < u[r]) lo += s;
            lo += (int)(skey32[r][rb + lo] < u[r]);    // resolve 31 vs 32
            const float4 S = srun[r][w * 33 + lo];
            den4[r].x += S.x; den4[r].y += S.y; den4[r].z += S.z; den4[r].w += S.w;
        }
    }

    float bmax[2];
    #pragma unroll
    for (int r = 0; r < 2; ++r) {
        bmax[r] = s_runmax[r][0];
        #pragma unroll
        for (int w = 1; w < 8; ++w) bmax[r] = fmaxf(bmax[r], s_runmax[r][w]);
    }

    // Candidates per row (per-warp regions)
    #pragma unroll
    for (int r = 0; r < 2; ++r) {
        const bool flag = (tm[r] > 0.0f) && (e[r] > TAU * den4[r].x);
        const unsigned int bal = __ballot_sync(0xffffffffu, flag);
        if (lane == 0) warp_cc[r][w8] = __popc(bal);
        if (flag) {
            const int pos = __popc(bal & ((1u << lane) - 1u));
            candTE[r][w8 * 32 + pos] = make_float2(tm[r], e[r]);
            candI [r][w8 * 32 + pos] = i;
        }
    }
    __syncthreads();                                   // bar2

    // Contributions (both rows; independent MUFU/FMA chains)
    float contrib[2];
    #pragma unroll
    for (int r = 0; r < 2; ++r) {
        contrib[r] = 0.0f;
        const bool elim = (tm[r] > 0.0f) && (tm[r] < bmax[r]);
        if (elim) {
            const float den = den4[r].x;
            const float id  = __fdividef(1.0f, den);
            const float id2 = id * id;
            float part2 = den4[r].x * id + 0.5f * (den4[r].y * id2)
                        + (1.0f / 3.0f) * (den4[r].z * (id2 * id))
                        + 0.25f * (den4[r].w * (id2 * id2));
            part2 -= poly_mlog1m(e[r] * id);           // remove self term exactly

            #pragma unroll
            for (int w = 0; w < 8; ++w) {
                const int nw = warp_cc[r][w];
                for (int q = 0; q < nw; ++q) {
                    const float2 te = candTE[r][w * 32 + q];
                    const float xx = te.y * id;
                    if (te.x >= tm[r] && xx > TAU && candI[r][w * 32 + q] != i)
                        contrib[r] += -__logf(fmaxf(1.0f + EPS_F - xx, 2.0f * EPS_F))
                                      - poly_mlog1m(xx);
                }
            }
            const float w = fminf(fmaxf((bmax[r] - tm[r]) / fmaxf(bmax[r], 1.0f), 0.0f), 1.0f);
            contrib[r] = (__logf(den) - p[r] + part2 + contrib[r]) * w;
        }
    }

    // Warp reduce both rows, then block publish
    #pragma unroll
    for (int o = 16; o > 0; o >>= 1) {
        contrib[0] += __shfl_xor_sync(0xffffffffu, contrib[0], o);
        contrib[1] += __shfl_xor_sync(0xffffffffu, contrib[1], o);
    }
    if (lane == 0) { sredA[0][w8] = contrib[0]; sredA[1][w8] = contrib[1]; }
    __syncthreads();                                   // bar3

    // Warp 0 finishes: publish both rows; last ticket-holder reduces all rows
    if (w8 == 0) {
        unsigned int tk = 0;
        if (lane == 0) {
            #pragma unroll
            for (int r = 0; r < 2; ++r) {
                float s = 0.0f;
                int vcnt = 0;
                #pragma unroll
                for (int k = 0; k < 8; ++k) { s += sredA[r][k]; vcnt += warp_vc[r][k]; }
                const float flagv = (vcnt >= 2) ? 1.0f : 0.0f;
                g_tf[blk * 2 + r] = make_float2(s * flagv, flagv);
            }
            __threadfence();
            tk = atomicAdd(&g_ticket, 1u);
        }
        tk = __shfl_sync(0xffffffffu, tk, 0);
        if (tk == (unsigned int)gridDim.x - 1u) {      // last block's warp 0
            if (lane == 0) g_ticket = 0;               // reset for next replay
            __threadfence();
            float T = 0.0f, F = 0.0f;
            #pragma unroll
            for (int k = 0; k < 8; ++k) {              // fixed order: deterministic
                const float2 tf = g_tf[lane * 8 + k];
                T += tf.x; F += tf.y;
            }
            #pragma unroll
            for (int o = 16; o > 0; o >>= 1) {
                T += __shfl_xor_sync(0xffffffffu, T, o);
                F += __shfl_xor_sync(0xffffffffu, F, o);
            }
            if (lane == 0) out[0] = T / fmaxf(F, 1.0f);
        }
    }
}

extern "C" void kernel_launch(void* const* d_in, const int* in_sizes, int n_in,
                              void* d_out, int out_size) {
    (void)in_sizes; (void)n_in; (void)out_size;
    const float*        pred   = (const float*)d_in[0];
    const float*        target = (const float*)d_in[1];
    const unsigned int* mask   = (const unsigned int*)d_in[2];

    cox_kernel<<<B_DIM / 2, N_DIM>>>(pred, target, mask, (float*)d_out);
}